// round 6
// baseline (speedup 1.0000x reference)
#include <cuda_runtime.h>
#include <math.h>

#define BATCH 8
#define PP    100
#define NNEG  50000
#define DD    128
#define KTOP  512

#define NTILE 64     // n columns per block in sim kernel
#define KC    32     // k chunk

#define CANDCAP 2048

// 160 MB scratch: similarity values, stored as order-preserving uint32
__device__ unsigned int g_simu[(size_t)BATCH * PP * NNEG];

// ---------- helpers ----------
__device__ __forceinline__ unsigned int f2ord(float f) {
    unsigned int u = __float_as_uint(f);
    return (u & 0x80000000u) ? ~u : (u | 0x80000000u);
}

__device__ __forceinline__ unsigned long long pack2(float lo, float hi) {
    unsigned long long r;
    asm("mov.b64 %0, {%1, %2};" : "=l"(r) : "f"(lo), "f"(hi));
    return r;
}
__device__ __forceinline__ void unpack2(unsigned long long v, float& lo, float& hi) {
    asm("mov.b64 {%0, %1}, %2;" : "=f"(lo), "=f"(hi) : "l"(v));
}
__device__ __forceinline__ void ffma2(unsigned long long& d, unsigned long long a, unsigned long long b) {
    asm("fma.rn.f32x2 %0, %1, %2, %0;" : "+l"(d) : "l"(a), "l"(b));
}

// ============================================================
// Kernel 1: sim[b,p,n] = fea0[b,p,:] . neg[b,n,:]  (fp32, f32x2 packed)
// Block tile: 100 p x 64 n, full K=128 in 4 chunks of 32.
// blockDim (16,10) = 160 threads; thread tile: 5 p-pairs x 4 n.
// Writes order-preserving uint32 to g_simu.
// ============================================================
__global__ __launch_bounds__(160) void sim_kernel(
    const float* __restrict__ fea0, const float* __restrict__ neg)
{
    __shared__ __align__(16) float sA[KC][PP];     // 12.8 KB  (k-major, p contiguous)
    __shared__ __align__(16) float sB[KC][NTILE];  // 8 KB

    const int b  = blockIdx.y;
    const int n0 = blockIdx.x * NTILE;
    const int tx = threadIdx.x;   // 0..15 (n)
    const int ty = threadIdx.y;   // 0..9  (p groups of 10)
    const int tid = ty * 16 + tx;

    unsigned long long acc[5][4];
#pragma unroll
    for (int i = 0; i < 5; i++)
#pragma unroll
        for (int j = 0; j < 4; j++) acc[i][j] = 0ULL;

    const float* feaB = fea0 + (size_t)b * PP * DD;
    const float* negB = neg  + (size_t)b * NNEG * DD;

    for (int k0 = 0; k0 < DD; k0 += KC) {
        // load A chunk: 100 x 32
        for (int idx = tid; idx < PP * KC; idx += 160) {
            int p  = idx >> 5;
            int kk = idx & 31;
            sA[kk][p] = feaB[p * DD + k0 + kk];
        }
        // load B chunk: 64 rows x 32 k, via float4
        for (int idx = tid; idx < NTILE * (KC / 4); idx += 160) {
            int n  = idx >> 3;
            int kq = idx & 7;
            int gn = n0 + n;
            float4 v = make_float4(0.f, 0.f, 0.f, 0.f);
            if (gn < NNEG)
                v = *(const float4*)(negB + (size_t)gn * DD + k0 + kq * 4);
            sB[kq * 4 + 0][n] = v.x;
            sB[kq * 4 + 1][n] = v.y;
            sB[kq * 4 + 2][n] = v.z;
            sB[kq * 4 + 3][n] = v.w;
        }
        __syncthreads();

#pragma unroll
        for (int kk = 0; kk < KC; kk++) {
            unsigned long long bv[4];
#pragma unroll
            for (int j = 0; j < 4; j++) {
                float x = sB[kk][tx + 16 * j];
                bv[j] = pack2(x, x);
            }
            unsigned long long av[5];
#pragma unroll
            for (int i = 0; i < 5; i++)
                av[i] = *(const unsigned long long*)&sA[kk][ty * 10 + 2 * i];
#pragma unroll
            for (int i = 0; i < 5; i++)
#pragma unroll
                for (int j = 0; j < 4; j++)
                    ffma2(acc[i][j], av[i], bv[j]);
        }
        __syncthreads();
    }

    unsigned int* simB = g_simu + (size_t)b * PP * NNEG;
#pragma unroll
    for (int j = 0; j < 4; j++) {
        int n = n0 + tx + 16 * j;
        if (n < NNEG) {
#pragma unroll
            for (int i = 0; i < 5; i++) {
                float lo, hi;
                unpack2(acc[i][j], lo, hi);
                int p = ty * 10 + 2 * i;
                simB[(size_t)p * NNEG + n]       = f2ord(lo);
                simB[(size_t)(p + 1) * NNEG + n] = f2ord(hi);
            }
        }
    }
}

// ============================================================
// Kernel 2: per (b,p): exact top-512 select (radix on candidates),
// posW = fea0 @ W, bilinear scores on selected, softmax-weighted sum.
// One block (512 threads) per row, row cached in smem.
// ============================================================
// smem words: srow 50000, ck 2048, ci 2048, hist 256, ss 256,
//             sel 512, scores 512, red 512, posw 128, fearow 128, ctrl 16
#define SMEM_WORDS (NNEG + CANDCAP + CANDCAP + 256 + 256 + 512 + 512 + 512 + 128 + 128 + 16)
#define SMEM_BYTES (SMEM_WORDS * 4)

__global__ __launch_bounds__(512) void select_kernel(
    const float* __restrict__ fea0, const float* __restrict__ neg,
    const float* __restrict__ W, const float* __restrict__ bias_p,
    const float* __restrict__ scale_p, float* __restrict__ out)
{
    extern __shared__ unsigned int sm[];
    unsigned int* srow   = sm;                    // 50000
    unsigned int* ck     = srow + NNEG;           // 2048 candidate keys
    unsigned int* ci     = ck + CANDCAP;          // 2048 candidate indices
    int*          hist   = (int*)(ci + CANDCAP);  // 256
    int*          ss     = hist + 256;            // 256 suffix sums
    int*          sel    = ss + 256;              // 512 selected indices
    float*        scores = (float*)(sel + 512);   // 512
    float*        red    = scores + 512;          // 512 reduction buffer
    float*        posw   = red + 512;             // 128
    float*        fearow = posw + 128;            // 128
    int*          ctrl   = (int*)(fearow + 128);  // counters

    const int p = blockIdx.x;
    const int b = blockIdx.y;
    const int tid = threadIdx.x;

    const unsigned int* gsrow = g_simu + (size_t)(b * PP + p) * NNEG;

    // load sim row (uint4 coalesced) + fea row
    for (int i = tid; i < NNEG / 4; i += 512)
        ((uint4*)srow)[i] = ((const uint4*)gsrow)[i];
    if (tid < DD)
        fearow[tid] = fea0[(size_t)(b * PP + p) * DD + tid];
    __syncthreads();

    // sigma^2 = ||fea0 row||^2
    if (tid < 128) red[tid] = fearow[tid] * fearow[tid];
    __syncthreads();
    for (int off = 64; off > 0; off >>= 1) {
        if (tid < off) red[tid] += red[tid + off];
        __syncthreads();
    }
    float sigma = sqrtf(red[0]);
    __syncthreads();

    // posW[e] = sum_d fearow[d] * W[d][e]   (tid<128)
    if (tid < DD) {
        float a = 0.f;
#pragma unroll 8
        for (int d = 0; d < DD; d++) a = fmaf(fearow[d], W[d * DD + tid], a);
        posw[tid] = a;
    }

    // --- threshold search: want 512 <= count(u > Tu) <= 2048 ---
    // first guess = Gaussian quantile (expected count ~1200), then uint bisection
    unsigned int lo = 0u, hi = 0xFFFFFFFFu;
    unsigned int Tu = f2ord(1.977f * sigma);
    int count = 0;
    for (int it = 0; it < 48; ++it) {
        __syncthreads();
        if (tid == 0) ctrl[0] = 0;
        __syncthreads();
        int c = 0;
        for (int i = tid; i < NNEG; i += 512) c += (srow[i] > Tu);
#pragma unroll
        for (int o = 16; o > 0; o >>= 1) c += __shfl_down_sync(0xffffffffu, c, o);
        if ((tid & 31) == 0) atomicAdd(&ctrl[0], c);
        __syncthreads();
        count = ctrl[0];
        if (count >= KTOP && count <= CANDCAP) break;
        if (count > CANDCAP) lo = Tu; else hi = Tu;
        Tu = lo + ((hi - lo) >> 1);
    }

    // --- collect candidates ---
    __syncthreads();
    if (tid == 0) ctrl[1] = 0;
    __syncthreads();
    for (int i = tid; i < NNEG; i += 512) {
        unsigned int u = srow[i];
        if (u > Tu) {
            int s = atomicAdd(&ctrl[1], 1);
            if (s < CANDCAP) { ck[s] = u; ci[s] = (unsigned int)i; }
        }
    }
    __syncthreads();
    int C = min(ctrl[1], CANDCAP);

    // --- byte radix select: exact threshold key among candidates ---
    unsigned int prefix = 0u, decided = 0u;
    int remaining = KTOP;
    for (int shift = 24; shift >= 0; shift -= 8) {
        if (tid < 256) hist[tid] = 0;
        __syncthreads();
        for (int i = tid; i < C; i += 512) {
            unsigned int k = ck[i];
            if ((k & decided) == prefix)
                atomicAdd(&hist[(k >> shift) & 255], 1);
        }
        __syncthreads();
        if (tid < 256) ss[tid] = hist[tid];
        __syncthreads();
        // suffix sums (Hillis-Steele)
        for (int off = 1; off < 256; off <<= 1) {
            int v = 0;
            if (tid < 256) { v = ss[tid]; if (tid + off < 256) v += ss[tid + off]; }
            __syncthreads();
            if (tid < 256) ss[tid] = v;
            __syncthreads();
        }
        if (tid < 256) {
            int above = (tid == 255) ? 0 : ss[tid + 1];
            if (ss[tid] >= remaining && above < remaining) {
                ctrl[2] = tid;
                ctrl[3] = above;
            }
        }
        __syncthreads();
        prefix  |= ((unsigned int)ctrl[2]) << shift;
        decided |= (0xFFu << shift);
        remaining -= ctrl[3];
        __syncthreads();
    }

    // --- final selection of exactly 512 indices ---
    const unsigned int Tstar = prefix;
    const int need_eq  = remaining;
    const int count_gt = KTOP - remaining;
    if (tid == 0) { ctrl[4] = 0; ctrl[5] = 0; }
    __syncthreads();
    for (int i = tid; i < C; i += 512) {
        unsigned int u = ck[i];
        if (u > Tstar) {
            int s = atomicAdd(&ctrl[4], 1);
            sel[s] = (int)ci[i];
        } else if (u == Tstar) {
            int e = atomicAdd(&ctrl[5], 1);
            if (e < need_eq) sel[count_gt + e] = (int)ci[i];
        }
    }
    __syncthreads();

    // --- bilinear scores for the 512 selected negatives ---
    const float bias = *bias_p;
    const float scale = log1pf(__expf(*scale_p));
    const int wid = tid >> 5, lane = tid & 31;
    const float4 pw = *(const float4*)&posw[lane * 4];
    for (int k = wid; k < KTOP; k += 16) {
        const float4* nr = (const float4*)(neg + ((size_t)b * NNEG + sel[k]) * DD);
        float4 v = nr[lane];
        float d = v.x * pw.x + v.y * pw.y + v.z * pw.z + v.w * pw.w;
#pragma unroll
        for (int o = 16; o > 0; o >>= 1) d += __shfl_down_sync(0xffffffffu, d, o);
        if (lane == 0) scores[k] = d + bias;
    }
    __syncthreads();

    // --- softmax-weighted aggregation: out = sum softmax(scale*s) * s ---
    const float s = scores[tid];
    red[tid] = s;
    __syncthreads();
    for (int off = 256; off > 0; off >>= 1) {
        if (tid < off) red[tid] = fmaxf(red[tid], red[tid + off]);
        __syncthreads();
    }
    const float m = red[0];
    __syncthreads();
    const float e = __expf(scale * (s - m));
    red[tid] = e;
    __syncthreads();
    for (int off = 256; off > 0; off >>= 1) {
        if (tid < off) red[tid] += red[tid + off];
        __syncthreads();
    }
    const float Z = red[0];
    __syncthreads();
    red[tid] = e * s;
    __syncthreads();
    for (int off = 256; off > 0; off >>= 1) {
        if (tid < off) red[tid] += red[tid + off];
        __syncthreads();
    }
    if (tid == 0) out[b * PP + p] = red[0] / Z;
}

// ============================================================
extern "C" void kernel_launch(void* const* d_in, const int* in_sizes, int n_in,
                              void* d_out, int out_size)
{
    const float* fea0  = (const float*)d_in[0];
    const float* neg   = (const float*)d_in[1];
    const float* W     = (const float*)d_in[2];
    const float* bias  = (const float*)d_in[3];
    const float* scale = (const float*)d_in[4];
    float* out = (float*)d_out;

    cudaFuncSetAttribute(select_kernel,
                         cudaFuncAttributeMaxDynamicSharedMemorySize, SMEM_BYTES);

    dim3 g1((NNEG + NTILE - 1) / NTILE, BATCH);
    sim_kernel<<<g1, dim3(16, 10)>>>(fea0, neg);

    dim3 g2(PP, BATCH);
    select_kernel<<<g2, 512, SMEM_BYTES>>>(fea0, neg, W, bias, scale, out);
}